// round 8
// baseline (speedup 1.0000x reference)
#include <cuda_runtime.h>
#include <cuda_fp16.h>
#include <cstdint>

#define BB     2
#define LL     2048
#define LTXT   1024
#define DMODEL 512
#define NHEAD  8
#define DHEAD  64
#define WSZ    (DMODEL*DMODEL)

// Scratch (device globals; no allocations allowed)
__device__ __half g_xq[BB*LL*DMODEL];         // fp16 of input q
__device__ __half g_xk[BB*LL*DMODEL];         // fp16 of input k
__device__ __half g_xv[BB*LL*DMODEL];         // fp16 of input v
__device__ __half g_wh[4*WSZ];                // fp16 of wq,wk,wv,wo
__device__ __half g_qh[BB*NHEAD*LL*DHEAD];    // [bh][l][d], pre-scaled 1/8
__device__ __half g_kh[BB*NHEAD*LL*DHEAD];    // [bh][l][d]
__device__ __half g_vh[BB*NHEAD*LL*DHEAD];    // TRANSPOSED [bh][d][l], pre-mul coef
__device__ __half g_attnh[BB*LL*DMODEL];      // [l][512]
__device__ float  g_coef[BB*LL];

// ---------------------------------------------------------------------------
// Helpers
// ---------------------------------------------------------------------------
__device__ __forceinline__ uint32_t pk(float lo, float hi) {
    __half2 h = __floats2half2_rn(lo, hi);
    return *reinterpret_cast<uint32_t*>(&h);
}
__device__ __forceinline__ void mma16(float* c,
    uint32_t a0, uint32_t a1, uint32_t a2, uint32_t a3,
    uint32_t b0, uint32_t b1)
{
    asm("mma.sync.aligned.m16n8k16.row.col.f32.f16.f16.f32 "
        "{%0,%1,%2,%3},{%4,%5,%6,%7},{%8,%9},{%0,%1,%2,%3};"
        : "+f"(c[0]), "+f"(c[1]), "+f"(c[2]), "+f"(c[3])
        : "r"(a0), "r"(a1), "r"(a2), "r"(a3), "r"(b0), "r"(b1));
}
__device__ __forceinline__ void cp_async16(uint32_t saddr, const void* gptr) {
    asm volatile("cp.async.cg.shared.global [%0], [%1], 16;" :: "r"(saddr), "l"(gptr));
}
__device__ __forceinline__ void cp_commit() {
    asm volatile("cp.async.commit_group;");
}

// ---------------------------------------------------------------------------
// fp32 -> fp16 bulk convert (7 tensors)
// ---------------------------------------------------------------------------
struct CvtArgs {
    const float* src[7];
    __half*      dst[7];
    int          n4[7];      // count of float4 elements
};

__global__ void __launch_bounds__(256) cvt_kernel(CvtArgs a)
{
    const int z = blockIdx.y;
    const float4* s = (const float4*)a.src[z];
    uint2* d = (uint2*)a.dst[z];
    const int n4 = a.n4[z];
    for (int i = blockIdx.x*256 + threadIdx.x; i < n4; i += gridDim.x*256) {
        float4 v = s[i];
        d[i] = make_uint2(pk(v.x, v.y), pk(v.z, v.w));
    }
}

// ---------------------------------------------------------------------------
// Mask -> per-position post-softmax coefficient. coef==0 iff position masked.
// ---------------------------------------------------------------------------
__global__ void coef_kernel(const float* __restrict__ tm, const float* __restrict__ am)
{
    int b = blockIdx.x;
    int t = threadIdx.x;              // 1024 threads
    float tv = tm[b*LTXT + t];
    float av = am[b*LTXT + t];
    float ts = tv, as_ = av;
    #pragma unroll
    for (int o = 16; o; o >>= 1) {
        ts  += __shfl_xor_sync(0xffffffffu, ts,  o);
        as_ += __shfl_xor_sync(0xffffffffu, as_, o);
    }
    __shared__ float st[32], sa[32];
    int warp = t >> 5, lane = t & 31;
    if (lane == 0) { st[warp] = ts; sa[warp] = as_; }
    __syncthreads();
    if (warp == 0) {
        ts = st[lane]; as_ = sa[lane];
        #pragma unroll
        for (int o = 16; o; o >>= 1) {
            ts  += __shfl_xor_sync(0xffffffffu, ts,  o);
            as_ += __shfl_xor_sync(0xffffffffu, as_, o);
        }
        if (lane == 0) { st[0] = ts; sa[0] = as_; }
    }
    __syncthreads();
    float tsum = st[0], asum = sa[0], tot = tsum + asum;
    g_coef[b*LL + t]        = tv * (tot / (2.0f * tsum));
    g_coef[b*LL + LTXT + t] = av * (tot / (2.0f * asum));
}

// ---------------------------------------------------------------------------
// FP16 TC GEMM, 3-stage cp.async, BK=64, one __syncthreads per iteration.
// Block 128x64, 256 threads (8 warps 4x2), warp 32x32, m16n8k16.
// Shared by QKV (fp16 out, modes) and OUT (f32 out) via template-ish branch.
// ---------------------------------------------------------------------------
#define GAP 36                   // words per 64-half row (128B data + 16B pad)
#define XST (128*GAP)
#define WST (64*GAP)
#define GEMM_SMEM (3*(XST + WST)*4)
#define NKC (DMODEL/64)          // 8 iterations

struct QkvArgs {
    const __half* X[3];
    const __half* W[3];
    const float*  bias[3];
    __half*       Y[3];
    int           mode[3];       // 1=Q, 2=K, 3=V(transposed)
    const float*  coef;
};

template<typename EPI>
__device__ __forceinline__ void gemm_core(
    const __half* __restrict__ X, const __half* __restrict__ W,
    uint32_t* smem, int m0, int n0, EPI epi)
{
    uint32_t* sX = smem;
    uint32_t* sW = smem + 3*XST;

    const int tid  = threadIdx.x;
    const int warp = tid >> 5, lane = tid & 31;
    const int qr = lane >> 2, qc = lane & 3;
    const int wm = (warp >> 1) * 32;
    const int wn = (warp & 1) * 32;

    const uint32_t bX = (uint32_t)__cvta_generic_to_shared(sX);
    const uint32_t bW = (uint32_t)__cvta_generic_to_shared(sW);

    auto prefetch = [&](int buf, int k0) {
        #pragma unroll
        for (int i = 0; i < 4; i++) {
            int s = tid + i*256;            // 1024 chunks: row=s>>3, ch=s&7
            int r = s >> 3, ch = s & 7;
            cp_async16(bX + (buf*XST + r*GAP + ch*4)*4,
                       X + (size_t)(m0 + r)*DMODEL + k0 + ch*8);
        }
        #pragma unroll
        for (int i = 0; i < 2; i++) {
            int s = tid + i*256;            // 512 chunks
            int r = s >> 3, ch = s & 7;
            cp_async16(bW + (buf*WST + r*GAP + ch*4)*4,
                       W + (size_t)(n0 + r)*DMODEL + k0 + ch*8);
        }
        cp_commit();
    };

    float c[2][4][4] = {};

    prefetch(0, 0);
    prefetch(1, 64);
    #pragma unroll 1
    for (int kc = 0; kc < NKC; kc++) {
        if (kc + 1 < NKC) asm volatile("cp.async.wait_group 1;");
        else              asm volatile("cp.async.wait_group 0;");
        __syncthreads();
        if (kc + 2 < NKC) prefetch((kc+2)%3, (kc+2)*64);

        const uint32_t* Xb = sX + (kc%3)*XST;
        const uint32_t* Wb = sW + (kc%3)*WST;
        #pragma unroll
        for (int kk = 0; kk < 4; kk++) {
            uint32_t a[2][4];
            #pragma unroll
            for (int mi = 0; mi < 2; mi++) {
                int r = wm + mi*16 + qr;
                a[mi][0] = Xb[(r  )*GAP + kk*8 + qc];
                a[mi][1] = Xb[(r+8)*GAP + kk*8 + qc];
                a[mi][2] = Xb[(r  )*GAP + kk*8 + qc + 4];
                a[mi][3] = Xb[(r+8)*GAP + kk*8 + qc + 4];
            }
            #pragma unroll
            for (int nj = 0; nj < 4; nj++) {
                int r = wn + nj*8 + qr;
                uint32_t b0 = Wb[r*GAP + kk*8 + qc];
                uint32_t b1 = Wb[r*GAP + kk*8 + qc + 4];
                mma16(c[0][nj], a[0][0], a[0][1], a[0][2], a[0][3], b0, b1);
                mma16(c[1][nj], a[1][0], a[1][1], a[1][2], a[1][3], b0, b1);
            }
        }
    }

    #pragma unroll
    for (int mi = 0; mi < 2; mi++) {
        int row0 = m0 + wm + mi*16 + qr;
        #pragma unroll
        for (int nj = 0; nj < 4; nj++) {
            int col = n0 + wn + nj*8 + qc*2;
            epi(row0, col, c[mi][nj]);
        }
    }
}

__global__ void __launch_bounds__(256) gemm_qkv(QkvArgs args)
{
    extern __shared__ uint32_t smg[];
    const int z = blockIdx.z;
    const float* B = args.bias[z];
    __half* Y = args.Y[z];
    const int mode = args.mode[z];
    const float* coef = args.coef;

    gemm_core(args.X[z], args.W[z], smg, blockIdx.y*128, blockIdx.x*64,
        [&](int row0, int col, float* cc) {
            int row1 = row0 + 8;
            float b0 = B[col], b1 = B[col+1];
            float v00 = cc[0] + b0, v01 = cc[1] + b1;
            float v10 = cc[2] + b0, v11 = cc[3] + b1;
            int h = col >> 6, d = col & 63;
            int bi0 = row0 >> 11, l0 = row0 & 2047;
            int bi1 = row1 >> 11, l1 = row1 & 2047;
            if (mode == 1) {
                v00 *= 0.125f; v01 *= 0.125f; v10 *= 0.125f; v11 *= 0.125f;
            }
            if (mode == 3) {
                float c0 = coef[row0], c1 = coef[row1];
                __half* p = Y + ((size_t)(bi0*NHEAD + h)*DHEAD + d)*LL;  // [bh][d][l]
                p[l0]      = __float2half(v00*c0);
                p[LL + l0] = __float2half(v01*c0);
                p[l1]      = __float2half(v10*c1);
                p[LL + l1] = __float2half(v11*c1);
            } else {
                *(__half2*)(Y + ((size_t)(bi0*NHEAD + h)*LL + l0)*DHEAD + d) =
                    __floats2half2_rn(v00, v01);
                *(__half2*)(Y + ((size_t)(bi1*NHEAD + h)*LL + l1)*DHEAD + d) =
                    __floats2half2_rn(v10, v11);
            }
        });
}

__global__ void __launch_bounds__(256) gemm_out(
    const __half* __restrict__ Xh, const __half* __restrict__ Wh,
    const float* __restrict__ B, float* __restrict__ Y)
{
    extern __shared__ uint32_t smg[];
    gemm_core(Xh, Wh, smg, blockIdx.y*128, blockIdx.x*64,
        [&](int row0, int col, float* cc) {
            float b0 = B[col], b1 = B[col+1];
            *(float2*)(Y + (size_t)row0*DMODEL + col)     = make_float2(cc[0]+b0, cc[1]+b1);
            *(float2*)(Y + (size_t)(row0+8)*DMODEL + col) = make_float2(cc[2]+b0, cc[3]+b1);
        });
}

// ---------------------------------------------------------------------------
// Fused attention: fp16 m16n8k16, BM=128, BN=64, 256 threads, 2 CTAs/SM.
// 3-stage cp.async ring for K/V/coef; P fragments packed directly from exps.
// ---------------------------------------------------------------------------
#define AP 36
#define KT (64*AP)
#define ATTN_SMEM ((6*KT + 3*64) * 4)
#define NT (LL/64)

__global__ void __launch_bounds__(256, 2) attn_kernel()
{
    extern __shared__ uint32_t smu[];
    uint32_t* Ks  = smu;                    // [3][64key][AP]
    uint32_t* Vs  = smu + 3*KT;             // [3][64d][AP]  (V^T)
    float*    kok = (float*)(smu + 6*KT);   // [3][64]

    const int tid  = threadIdx.x;
    const int warp = tid >> 5, lane = tid & 31;
    const int qr = lane >> 2, qc = lane & 3;
    const int bh = blockIdx.y, bi = bh >> 3, h = bh & 7;
    const int q0 = blockIdx.x * 128;
    const int wrow = warp * 16;

    const __half* kbase = g_kh + (size_t)bh * LL * DHEAD;   // [l][d]
    const __half* vbase = g_vh + (size_t)bh * DHEAD * LL;   // [d][l]
    const float*  cbase = g_coef + bi*LL;

    const uint32_t sK = (uint32_t)__cvta_generic_to_shared(Ks);
    const uint32_t sV = (uint32_t)__cvta_generic_to_shared(Vs);
    const uint32_t sC = (uint32_t)__cvta_generic_to_shared(kok);

    auto prefetch = [&](int buf, int k0) {
        #pragma unroll
        for (int i = 0; i < 2; i++) {
            int s = tid + i*256;
            int r = s >> 3, ch = s & 7;
            cp_async16(sK + (buf*KT + r*AP + ch*4)*4,
                       kbase + (size_t)(k0 + r)*DHEAD + ch*8);
            cp_async16(sV + (buf*KT + r*AP + ch*4)*4,
                       vbase + (size_t)r*LL + k0 + ch*8);
        }
        if (tid < 16)
            cp_async16(sC + (buf*64 + tid*4)*4, cbase + k0 + tid*4);
        cp_commit();
    };

    prefetch(0, 0);
    prefetch(1, 64);

    // ---- Q fragments straight from gmem (fp16, pre-scaled 1/8) ----
    const uint32_t* qrow0 =
        (const uint32_t*)(g_qh + ((size_t)bh*LL + q0 + wrow + qr)*DHEAD);
    const uint32_t* qrow1 = qrow0 + 8*(DHEAD/2);
    uint32_t aQ[4][4];
    #pragma unroll
    for (int kk = 0; kk < 4; kk++) {
        aQ[kk][0] = qrow0[kk*8 + qc];
        aQ[kk][1] = qrow1[kk*8 + qc];
        aQ[kk][2] = qrow0[kk*8 + qc + 4];
        aQ[kk][3] = qrow1[kk*8 + qc + 4];
    }
    const bool q0ok = (cbase[q0 + wrow + qr]     != 0.0f);
    const bool q1ok = (cbase[q0 + wrow + qr + 8] != 0.0f);

    float o[8][4] = {};
    float m0 = -1e30f, m1 = -1e30f, l0 = 0.0f, l1 = 0.0f;

    #pragma unroll 1
    for (int t = 0; t < NT; t++) {
        if (t + 1 < NT) asm volatile("cp.async.wait_group 1;");
        else            asm volatile("cp.async.wait_group 0;");
        __syncthreads();
        if (t + 2 < NT) prefetch((t+2)%3, (t+2)*64);

        const uint32_t* Kb = Ks + (t%3)*KT;
        const uint32_t* Vb = Vs + (t%3)*KT;
        const float*    kb = kok + (t%3)*64;

        // ---- S = (Q/8) @ K^T ----
        float s[8][4] = {};
        #pragma unroll
        for (int kk = 0; kk < 4; kk++) {
            #pragma unroll
            for (int j = 0; j < 8; j++) {
                uint32_t b0 = Kb[(j*8+qr)*AP + kk*8 + qc];
                uint32_t b1 = Kb[(j*8+qr)*AP + kk*8 + qc + 4];
                mma16(s[j], aQ[kk][0], aQ[kk][1], aQ[kk][2], aQ[kk][3], b0, b1);
            }
        }

        // ---- mask ----
        #pragma unroll
        for (int j = 0; j < 8; j++) {
            bool kc0 = (kb[j*8 + qc*2    ] != 0.0f);
            bool kc1 = (kb[j*8 + qc*2 + 1] != 0.0f);
            if (!(q0ok && kc0)) s[j][0] = -10000.0f;
            if (!(q0ok && kc1)) s[j][1] = -10000.0f;
            if (!(q1ok && kc0)) s[j][2] = -10000.0f;
            if (!(q1ok && kc1)) s[j][3] = -10000.0f;
        }

        // ---- online softmax: row max ----
        float mx0 = -1e30f, mx1 = -1e30f;
        #pragma unroll
        for (int j = 0; j < 8; j++) {
            mx0 = fmaxf(mx0, fmaxf(s[j][0], s[j][1]));
            mx1 = fmaxf(mx1, fmaxf(s[j][2], s[j][3]));
        }
        mx0 = fmaxf(mx0, __shfl_xor_sync(0xffffffffu, mx0, 1));
        mx0 = fmaxf(mx0, __shfl_xor_sync(0xffffffffu, mx0, 2));
        mx1 = fmaxf(mx1, __shfl_xor_sync(0xffffffffu, mx1, 1));
        mx1 = fmaxf(mx1, __shfl_xor_sync(0xffffffffu, mx1, 2));
        float nm0 = fmaxf(m0, mx0), nm1 = fmaxf(m1, mx1);
        float sc0 = __expf(m0 - nm0), sc1 = __expf(m1 - nm1);
        m0 = nm0; m1 = nm1;

        #pragma unroll
        for (int j = 0; j < 8; j++) {
            o[j][0] *= sc0; o[j][1] *= sc0;
            o[j][2] *= sc1; o[j][3] *= sc1;
        }

        // ---- exp -> fp16 A-fragments (direct pack) -> PV mma ----
        float rs0 = 0.0f, rs1 = 0.0f;
        #pragma unroll
        for (int jj = 0; jj < 4; jj++) {
            float p00 = __expf(s[2*jj  ][0] - nm0);
            float p01 = __expf(s[2*jj  ][1] - nm0);
            float p02 = __expf(s[2*jj  ][2] - nm1);
            float p03 = __expf(s[2*jj  ][3] - nm1);
            float p10 = __expf(s[2*jj+1][0] - nm0);
            float p11 = __expf(s[2*jj+1][1] - nm0);
            float p12 = __expf(s[2*jj+1][2] - nm1);
            float p13 = __expf(s[2*jj+1][3] - nm1);
            rs0 += p00 + p01 + p10 + p11;
            rs1 += p02 + p03 + p12 + p13;

            uint32_t a0 = pk(p00, p01);
            uint32_t a1 = pk(p02, p03);
            uint32_t a2 = pk(p10, p11);
            uint32_t a3 = pk(p12, p13);

            #pragma unroll
            for (int nj = 0; nj < 8; nj++) {
                uint32_t b0 = Vb[(nj*8+qr)*AP + jj*8 + qc];
                uint32_t b1 = Vb[(nj*8+qr)*AP + jj*8 + qc + 4];
                mma16(o[nj], a0, a1, a2, a3, b0, b1);
            }
        }
        rs0 += __shfl_xor_sync(0xffffffffu, rs0, 1);
        rs0 += __shfl_xor_sync(0xffffffffu, rs0, 2);
        rs1 += __shfl_xor_sync(0xffffffffu, rs1, 1);
        rs1 += __shfl_xor_sync(0xffffffffu, rs1, 2);
        l0 = l0*sc0 + rs0;
        l1 = l1*sc1 + rs1;
    }

    // ---- epilogue: normalize, write fp16 [l][512] ----
    float inv0 = 1.0f / l0, inv1 = 1.0f / l1;
    int r0 = q0 + wrow + qr, r1 = r0 + 8;
    #pragma unroll
    for (int j = 0; j < 8; j++) {
        int d = h*64 + j*8 + qc*2;
        *(__half2*)(g_attnh + ((size_t)(bi*LL + r0))*DMODEL + d) =
            __floats2half2_rn(o[j][0]*inv0, o[j][1]*inv0);
        *(__half2*)(g_attnh + ((size_t)(bi*LL + r1))*DMODEL + d) =
            __floats2half2_rn(o[j][2]*inv1, o[j][3]*inv1);
    }
}

// ---------------------------------------------------------------------------
extern "C" void kernel_launch(void* const* d_in, const int* in_sizes, int n_in,
                              void* d_out, int out_size)
{
    const float* q  = (const float*)d_in[0];
    const float* k  = (const float*)d_in[1];
    const float* v  = (const float*)d_in[2];
    const float* tm = (const float*)d_in[3];
    const float* am = (const float*)d_in[4];
    const float* wq = (const float*)d_in[6];
    const float* bq = (const float*)d_in[7];
    const float* wk = (const float*)d_in[8];
    const float* bk = (const float*)d_in[9];
    const float* wv = (const float*)d_in[10];
    const float* bv = (const float*)d_in[11];
    const float* wo = (const float*)d_in[12];
    const float* bo = (const float*)d_in[13];
    float* out = (float*)d_out;

    __half *xq, *xk, *xv, *wh, *gq, *gk, *gv, *gattn;
    float *gcoef;
    cudaGetSymbolAddress((void**)&xq,    g_xq);
    cudaGetSymbolAddress((void**)&xk,    g_xk);
    cudaGetSymbolAddress((void**)&xv,    g_xv);
    cudaGetSymbolAddress((void**)&wh,    g_wh);
    cudaGetSymbolAddress((void**)&gq,    g_qh);
    cudaGetSymbolAddress((void**)&gk,    g_kh);
    cudaGetSymbolAddress((void**)&gv,    g_vh);
    cudaGetSymbolAddress((void**)&gattn, g_attnh);
    cudaGetSymbolAddress((void**)&gcoef, g_coef);

    cudaFuncSetAttribute(gemm_qkv, cudaFuncAttributeMaxDynamicSharedMemorySize, GEMM_SMEM);
    cudaFuncSetAttribute(gemm_out, cudaFuncAttributeMaxDynamicSharedMemorySize, GEMM_SMEM);
    cudaFuncSetAttribute(attn_kernel, cudaFuncAttributeMaxDynamicSharedMemorySize, ATTN_SMEM);

    const int NBIG = BB*LL*DMODEL/4;   // 524288 float4
    const int NW   = WSZ/4;            // 65536
    CvtArgs ca;
    ca.src[0] = q;  ca.dst[0] = xq;        ca.n4[0] = NBIG;
    ca.src[1] = k;  ca.dst[1] = xk;        ca.n4[1] = NBIG;
    ca.src[2] = v;  ca.dst[2] = xv;        ca.n4[2] = NBIG;
    ca.src[3] = wq; ca.dst[3] = wh;        ca.n4[3] = NW;
    ca.src[4] = wk; ca.dst[4] = wh + WSZ;  ca.n4[4] = NW;
    ca.src[5] = wv; ca.dst[5] = wh + 2*WSZ; ca.n4[5] = NW;
    ca.src[6] = wo; ca.dst[6] = wh + 3*WSZ; ca.n4[6] = NW;
    cvt_kernel<<<dim3(256, 7), 256>>>(ca);

    coef_kernel<<<2, 1024>>>(tm, am);   // must precede QKV (V epilogue reads coef)

    QkvArgs qkv;
    qkv.X[0] = xq; qkv.X[1] = xk; qkv.X[2] = xv;
    qkv.W[0] = wh; qkv.W[1] = wh + WSZ; qkv.W[2] = wh + 2*WSZ;
    qkv.bias[0] = bq; qkv.bias[1] = bk; qkv.bias[2] = bv;
    qkv.Y[0] = gq; qkv.Y[1] = gk; qkv.Y[2] = gv;
    qkv.mode[0] = 1; qkv.mode[1] = 2; qkv.mode[2] = 3;
    qkv.coef = gcoef;
    gemm_qkv<<<dim3(8, 32, 3), 256, GEMM_SMEM>>>(qkv);

    attn_kernel<<<dim3(16, 16), 256, ATTN_SMEM>>>();

    gemm_out<<<dim3(8, 32), 256, GEMM_SMEM>>>(gattn, wh + 3*WSZ, bo, out);
}

// round 9
// speedup vs baseline: 1.1313x; 1.1313x over previous
#include <cuda_runtime.h>
#include <cuda_fp16.h>
#include <cstdint>

#define BB     2
#define LL     2048
#define LTXT   1024
#define DMODEL 512
#define NHEAD  8
#define DHEAD  64
#define WSZ    (DMODEL*DMODEL)

// Scratch (device globals; no allocations allowed)
__device__ __half g_xq[BB*LL*DMODEL];
__device__ __half g_xk[BB*LL*DMODEL];
__device__ __half g_xv[BB*LL*DMODEL];
__device__ __half g_wh[4*WSZ];
__device__ __half g_qh[BB*NHEAD*LL*DHEAD];    // [bh][l][d], pre-scaled 1/8
__device__ __half g_kh[BB*NHEAD*LL*DHEAD];    // [bh][l][d]
__device__ __half g_vh[BB*NHEAD*LL*DHEAD];    // TRANSPOSED [bh][d][l], pre-mul coef
__device__ __half g_attnh[BB*LL*DMODEL];      // [l][512]
__device__ float  g_coef[BB*LL];

// ---------------------------------------------------------------------------
// Helpers
// ---------------------------------------------------------------------------
__device__ __forceinline__ uint32_t pk(float lo, float hi) {
    __half2 h = __floats2half2_rn(lo, hi);
    return *reinterpret_cast<uint32_t*>(&h);
}
__device__ __forceinline__ void mma16(float* c,
    uint32_t a0, uint32_t a1, uint32_t a2, uint32_t a3,
    uint32_t b0, uint32_t b1)
{
    asm("mma.sync.aligned.m16n8k16.row.col.f32.f16.f16.f32 "
        "{%0,%1,%2,%3},{%4,%5,%6,%7},{%8,%9},{%0,%1,%2,%3};"
        : "+f"(c[0]), "+f"(c[1]), "+f"(c[2]), "+f"(c[3])
        : "r"(a0), "r"(a1), "r"(a2), "r"(a3), "r"(b0), "r"(b1));
}
__device__ __forceinline__ void ldsm4(uint32_t& r0, uint32_t& r1,
                                      uint32_t& r2, uint32_t& r3, uint32_t addr)
{
    asm volatile("ldmatrix.sync.aligned.m8n8.x4.shared.b16 {%0,%1,%2,%3}, [%4];"
        : "=r"(r0), "=r"(r1), "=r"(r2), "=r"(r3) : "r"(addr));
}
__device__ __forceinline__ void cp_async16(uint32_t saddr, const void* gptr) {
    asm volatile("cp.async.cg.shared.global [%0], [%1], 16;" :: "r"(saddr), "l"(gptr));
}
__device__ __forceinline__ void cp_commit() {
    asm volatile("cp.async.commit_group;");
}

// ---------------------------------------------------------------------------
// fp32 -> fp16 bulk convert (7 tensors)
// ---------------------------------------------------------------------------
struct CvtArgs {
    const float* src[7];
    __half*      dst[7];
    int          n4[7];
};

__global__ void __launch_bounds__(256) cvt_kernel(CvtArgs a)
{
    const int z = blockIdx.y;
    const float4* s = (const float4*)a.src[z];
    uint2* d = (uint2*)a.dst[z];
    const int n4 = a.n4[z];
    for (int i = blockIdx.x*256 + threadIdx.x; i < n4; i += gridDim.x*256) {
        float4 v = s[i];
        d[i] = make_uint2(pk(v.x, v.y), pk(v.z, v.w));
    }
}

// ---------------------------------------------------------------------------
// Mask -> per-position post-softmax coefficient. coef==0 iff position masked.
// ---------------------------------------------------------------------------
__global__ void coef_kernel(const float* __restrict__ tm, const float* __restrict__ am)
{
    int b = blockIdx.x;
    int t = threadIdx.x;
    float tv = tm[b*LTXT + t];
    float av = am[b*LTXT + t];
    float ts = tv, as_ = av;
    #pragma unroll
    for (int o = 16; o; o >>= 1) {
        ts  += __shfl_xor_sync(0xffffffffu, ts,  o);
        as_ += __shfl_xor_sync(0xffffffffu, as_, o);
    }
    __shared__ float st[32], sa[32];
    int warp = t >> 5, lane = t & 31;
    if (lane == 0) { st[warp] = ts; sa[warp] = as_; }
    __syncthreads();
    if (warp == 0) {
        ts = st[lane]; as_ = sa[lane];
        #pragma unroll
        for (int o = 16; o; o >>= 1) {
            ts  += __shfl_xor_sync(0xffffffffu, ts,  o);
            as_ += __shfl_xor_sync(0xffffffffu, as_, o);
        }
        if (lane == 0) { st[0] = ts; sa[0] = as_; }
    }
    __syncthreads();
    float tsum = st[0], asum = sa[0], tot = tsum + asum;
    g_coef[b*LL + t]        = tv * (tot / (2.0f * tsum));
    g_coef[b*LL + LTXT + t] = av * (tot / (2.0f * asum));
}

// ---------------------------------------------------------------------------
// FP16 TC GEMM, 3-stage cp.async, BK=64, ldmatrix.x4 fragment loads.
// Block 128x64, 256 threads (8 warps 4x2), warp 32x32, m16n8k16.
// ---------------------------------------------------------------------------
#define GAP 36
#define XST (128*GAP)
#define WST (64*GAP)
#define GEMM_SMEM (3*(XST + WST)*4)
#define NKC (DMODEL/64)

struct QkvArgs {
    const __half* X[3];
    const __half* W[3];
    const float*  bias[3];
    __half*       Y[3];
    int           mode[3];
    const float*  coef;
};

template<typename EPI>
__device__ __forceinline__ void gemm_core(
    const __half* __restrict__ X, const __half* __restrict__ W,
    uint32_t* smem, int m0, int n0, EPI epi)
{
    uint32_t* sX = smem;
    uint32_t* sW = smem + 3*XST;

    const int tid  = threadIdx.x;
    const int warp = tid >> 5, lane = tid & 31;
    const int wm = (warp >> 1) * 32;
    const int wn = (warp & 1) * 32;
    const int rowin = lane & 7;
    const int selh  = lane >> 4;          // sel>>1
    const int sell  = (lane >> 3) & 1;    // sel&1

    const uint32_t bX = (uint32_t)__cvta_generic_to_shared(sX);
    const uint32_t bW = (uint32_t)__cvta_generic_to_shared(sW);

    auto prefetch = [&](int buf, int k0) {
        #pragma unroll
        for (int i = 0; i < 4; i++) {
            int s = tid + i*256;
            int r = s >> 3, ch = s & 7;
            cp_async16(bX + (buf*XST + r*GAP + ch*4)*4,
                       X + (size_t)(m0 + r)*DMODEL + k0 + ch*8);
        }
        #pragma unroll
        for (int i = 0; i < 2; i++) {
            int s = tid + i*256;
            int r = s >> 3, ch = s & 7;
            cp_async16(bW + (buf*WST + r*GAP + ch*4)*4,
                       W + (size_t)(n0 + r)*DMODEL + k0 + ch*8);
        }
        cp_commit();
    };

    // A matrices: m0=rows lo/k lo, m1=rows hi/k lo, m2=rows lo/k hi, m3=rows hi/k hi
    const uint32_t xoff = ((wm + sell*8 + rowin)*GAP + selh*4)*4;
    // B matrices: m0=nj even/k lo, m1=nj even/k hi, m2=nj odd/k lo, m3=nj odd/k hi
    const uint32_t woff = ((wn + selh*8 + rowin)*GAP + sell*4)*4;

    float c[2][4][4] = {};

    prefetch(0, 0);
    prefetch(1, 64);
    #pragma unroll 1
    for (int kc = 0; kc < NKC; kc++) {
        if (kc + 1 < NKC) asm volatile("cp.async.wait_group 1;");
        else              asm volatile("cp.async.wait_group 0;");
        __syncthreads();
        if (kc + 2 < NKC) prefetch((kc+2)%3, (kc+2)*64);

        const uint32_t xb = bX + (kc%3)*XST*4 + xoff;
        const uint32_t wb = bW + (kc%3)*WST*4 + woff;
        #pragma unroll
        for (int kk = 0; kk < 4; kk++) {
            uint32_t a[2][4];
            ldsm4(a[0][0], a[0][1], a[0][2], a[0][3], xb + kk*32);
            ldsm4(a[1][0], a[1][1], a[1][2], a[1][3], xb + 16*GAP*4 + kk*32);
            #pragma unroll
            for (int njp = 0; njp < 2; njp++) {
                uint32_t b0, b1, b2, b3;
                ldsm4(b0, b1, b2, b3, wb + njp*16*GAP*4 + kk*32);
                mma16(c[0][2*njp  ], a[0][0], a[0][1], a[0][2], a[0][3], b0, b1);
                mma16(c[1][2*njp  ], a[1][0], a[1][1], a[1][2], a[1][3], b0, b1);
                mma16(c[0][2*njp+1], a[0][0], a[0][1], a[0][2], a[0][3], b2, b3);
                mma16(c[1][2*njp+1], a[1][0], a[1][1], a[1][2], a[1][3], b2, b3);
            }
        }
    }

    const int qr = lane >> 2, qc = lane & 3;
    #pragma unroll
    for (int mi = 0; mi < 2; mi++) {
        int row0 = m0 + wm + mi*16 + qr;
        #pragma unroll
        for (int nj = 0; nj < 4; nj++) {
            int col = n0 + wn + nj*8 + qc*2;
            epi(row0, col, c[mi][nj]);
        }
    }
}

__global__ void __launch_bounds__(256) gemm_qkv(QkvArgs args)
{
    extern __shared__ uint32_t smg[];
    const int z = blockIdx.z;
    const float* B = args.bias[z];
    __half* Y = args.Y[z];
    const int mode = args.mode[z];
    const float* coef = args.coef;

    gemm_core(args.X[z], args.W[z], smg, blockIdx.y*128, blockIdx.x*64,
        [&](int row0, int col, float* cc) {
            int row1 = row0 + 8;
            float b0 = B[col], b1 = B[col+1];
            float v00 = cc[0] + b0, v01 = cc[1] + b1;
            float v10 = cc[2] + b0, v11 = cc[3] + b1;
            int h = col >> 6, d = col & 63;
            int bi0 = row0 >> 11, l0 = row0 & 2047;
            int bi1 = row1 >> 11, l1 = row1 & 2047;
            if (mode == 1) {
                v00 *= 0.125f; v01 *= 0.125f; v10 *= 0.125f; v11 *= 0.125f;
            }
            if (mode == 3) {
                float c0 = coef[row0], c1 = coef[row1];
                __half* p = Y + ((size_t)(bi0*NHEAD + h)*DHEAD + d)*LL;  // [bh][d][l]
                p[l0]      = __float2half(v00*c0);
                p[LL + l0] = __float2half(v01*c0);
                p[l1]      = __float2half(v10*c1);
                p[LL + l1] = __float2half(v11*c1);
            } else {
                *(__half2*)(Y + ((size_t)(bi0*NHEAD + h)*LL + l0)*DHEAD + d) =
                    __floats2half2_rn(v00, v01);
                *(__half2*)(Y + ((size_t)(bi1*NHEAD + h)*LL + l1)*DHEAD + d) =
                    __floats2half2_rn(v10, v11);
            }
        });
}

__global__ void __launch_bounds__(256) gemm_out(
    const __half* __restrict__ Xh, const __half* __restrict__ Wh,
    const float* __restrict__ B, float* __restrict__ Y)
{
    extern __shared__ uint32_t smg[];
    gemm_core(Xh, Wh, smg, blockIdx.y*128, blockIdx.x*64,
        [&](int row0, int col, float* cc) {
            float b0 = B[col], b1 = B[col+1];
            *(float2*)(Y + (size_t)row0*DMODEL + col)     = make_float2(cc[0]+b0, cc[1]+b1);
            *(float2*)(Y + (size_t)(row0+8)*DMODEL + col) = make_float2(cc[2]+b0, cc[3]+b1);
        });
}

// ---------------------------------------------------------------------------
// Fused attention: fp16 m16n8k16 + ldmatrix.x4.  BM=128, BN=64, 256 thr, 2 CTA/SM.
// ---------------------------------------------------------------------------
#define AP 36
#define KT (64*AP)
#define ATTN_SMEM ((6*KT + 3*64) * 4)
#define NT (LL/64)

__global__ void __launch_bounds__(256, 2) attn_kernel()
{
    extern __shared__ uint32_t smu[];
    uint32_t* Ks  = smu;                    // [3][64key][AP]
    uint32_t* Vs  = smu + 3*KT;             // [3][64d][AP]  (V^T)
    float*    kok = (float*)(smu + 6*KT);   // [3][64]

    const int tid  = threadIdx.x;
    const int warp = tid >> 5, lane = tid & 31;
    const int qr = lane >> 2, qc = lane & 3;
    const int bh = blockIdx.y, bi = bh >> 3, h = bh & 7;
    const int q0 = blockIdx.x * 128;
    const int wrow = warp * 16;
    const int rowin = lane & 7;
    const int selh  = lane >> 4;
    const int sell  = (lane >> 3) & 1;

    const __half* kbase = g_kh + (size_t)bh * LL * DHEAD;
    const __half* vbase = g_vh + (size_t)bh * DHEAD * LL;
    const float*  cbase = g_coef + bi*LL;

    const uint32_t sK = (uint32_t)__cvta_generic_to_shared(Ks);
    const uint32_t sV = (uint32_t)__cvta_generic_to_shared(Vs);
    const uint32_t sC = (uint32_t)__cvta_generic_to_shared(kok);

    auto prefetch = [&](int buf, int k0) {
        #pragma unroll
        for (int i = 0; i < 2; i++) {
            int s = tid + i*256;
            int r = s >> 3, ch = s & 7;
            cp_async16(sK + (buf*KT + r*AP + ch*4)*4,
                       kbase + (size_t)(k0 + r)*DHEAD + ch*8);
            cp_async16(sV + (buf*KT + r*AP + ch*4)*4,
                       vbase + (size_t)r*LL + k0 + ch*8);
        }
        if (tid < 16)
            cp_async16(sC + (buf*64 + tid*4)*4, cbase + k0 + tid*4);
        cp_commit();
    };

    prefetch(0, 0);
    prefetch(1, 64);

    // ---- Q fragments straight from gmem (fp16, pre-scaled 1/8) ----
    const uint32_t* qrow0 =
        (const uint32_t*)(g_qh + ((size_t)bh*LL + q0 + wrow + qr)*DHEAD);
    const uint32_t* qrow1 = qrow0 + 8*(DHEAD/2);
    uint32_t aQ[4][4];
    #pragma unroll
    for (int kk = 0; kk < 4; kk++) {
        aQ[kk][0] = qrow0[kk*8 + qc];
        aQ[kk][1] = qrow1[kk*8 + qc];
        aQ[kk][2] = qrow0[kk*8 + qc + 4];
        aQ[kk][3] = qrow1[kk*8 + qc + 4];
    }
    const bool q0ok = (cbase[q0 + wrow + qr]     != 0.0f);
    const bool q1ok = (cbase[q0 + wrow + qr + 8] != 0.0f);

    // ldmatrix lane offsets: m0/m1 = n-tile even (b0,b1), m2/m3 = n-tile odd
    const uint32_t fragoff = (((selh*8 + rowin)*AP) + sell*4)*4;

    float o[8][4] = {};
    float m0 = -1e30f, m1 = -1e30f, l0 = 0.0f, l1 = 0.0f;

    #pragma unroll 1
    for (int t = 0; t < NT; t++) {
        if (t + 1 < NT) asm volatile("cp.async.wait_group 1;");
        else            asm volatile("cp.async.wait_group 0;");
        __syncthreads();
        if (t + 2 < NT) prefetch((t+2)%3, (t+2)*64);

        const uint32_t kb_a = sK + (t%3)*KT*4 + fragoff;
        const uint32_t vb_a = sV + (t%3)*KT*4 + fragoff;
        const float*   kb   = kok + (t%3)*64;

        // ---- S = (Q/8) @ K^T ----
        float s[8][4] = {};
        #pragma unroll
        for (int kk = 0; kk < 4; kk++) {
            #pragma unroll
            for (int jp = 0; jp < 4; jp++) {
                uint32_t b0, b1, b2, b3;
                ldsm4(b0, b1, b2, b3, kb_a + (jp*16*AP)*4 + kk*32);
                mma16(s[2*jp  ], aQ[kk][0], aQ[kk][1], aQ[kk][2], aQ[kk][3], b0, b1);
                mma16(s[2*jp+1], aQ[kk][0], aQ[kk][1], aQ[kk][2], aQ[kk][3], b2, b3);
            }
        }

        // ---- mask ----
        #pragma unroll
        for (int j = 0; j < 8; j++) {
            bool kc0 = (kb[j*8 + qc*2    ] != 0.0f);
            bool kc1 = (kb[j*8 + qc*2 + 1] != 0.0f);
            if (!(q0ok && kc0)) s[j][0] = -10000.0f;
            if (!(q0ok && kc1)) s[j][1] = -10000.0f;
            if (!(q1ok && kc0)) s[j][2] = -10000.0f;
            if (!(q1ok && kc1)) s[j][3] = -10000.0f;
        }

        // ---- online softmax ----
        float mx0 = -1e30f, mx1 = -1e30f;
        #pragma unroll
        for (int j = 0; j < 8; j++) {
            mx0 = fmaxf(mx0, fmaxf(s[j][0], s[j][1]));
            mx1 = fmaxf(mx1, fmaxf(s[j][2], s[j][3]));
        }
        mx0 = fmaxf(mx0, __shfl_xor_sync(0xffffffffu, mx0, 1));
        mx0 = fmaxf(mx0, __shfl_xor_sync(0xffffffffu, mx0, 2));
        mx1 = fmaxf(mx1, __shfl_xor_sync(0xffffffffu, mx1, 1));
        mx1 = fmaxf(mx1, __shfl_xor_sync(0xffffffffu, mx1, 2));
        float nm0 = fmaxf(m0, mx0), nm1 = fmaxf(m1, mx1);
        float sc0 = __expf(m0 - nm0), sc1 = __expf(m1 - nm1);
        m0 = nm0; m1 = nm1;

        #pragma unroll
        for (int j = 0; j < 8; j++) {
            o[j][0] *= sc0; o[j][1] *= sc0;
            o[j][2] *= sc1; o[j][3] *= sc1;
        }

        // ---- exp -> fp16 A-fragments -> PV mma (ldmatrix V) ----
        float rs0 = 0.0f, rs1 = 0.0f;
        #pragma unroll
        for (int jj = 0; jj < 4; jj++) {
            float p00 = __expf(s[2*jj  ][0] - nm0);
            float p01 = __expf(s[2*jj  ][1] - nm0);
            float p02 = __expf(s[2*jj  ][2] - nm1);
            float p03 = __expf(s[2*jj  ][3] - nm1);
            float p10 = __expf(s[2*jj+1][0] - nm0);
            float p11 = __expf(s[2*jj+1][1] - nm0);
            float p12 = __expf(s[2*jj+1][2] - nm1);
            float p13 = __expf(s[2*jj+1][3] - nm1);
            rs0 += p00 + p01 + p10 + p11;
            rs1 += p02 + p03 + p12 + p13;

            uint32_t a0 = pk(p00, p01);
            uint32_t a1 = pk(p02, p03);
            uint32_t a2 = pk(p10, p11);
            uint32_t a3 = pk(p12, p13);

            #pragma unroll
            for (int njp = 0; njp < 4; njp++) {
                uint32_t b0, b1, b2, b3;
                ldsm4(b0, b1, b2, b3, vb_a + (njp*16*AP)*4 + jj*32);
                mma16(o[2*njp  ], a0, a1, a2, a3, b0, b1);
                mma16(o[2*njp+1], a0, a1, a2, a3, b2, b3);
            }
        }
        rs0 += __shfl_xor_sync(0xffffffffu, rs0, 1);
        rs0 += __shfl_xor_sync(0xffffffffu, rs0, 2);
        rs1 += __shfl_xor_sync(0xffffffffu, rs1, 1);
        rs1 += __shfl_xor_sync(0xffffffffu, rs1, 2);
        l0 = l0*sc0 + rs0;
        l1 = l1*sc1 + rs1;
    }

    // ---- epilogue ----
    float inv0 = 1.0f / l0, inv1 = 1.0f / l1;
    int r0 = q0 + wrow + qr, r1 = r0 + 8;
    #pragma unroll
    for (int j = 0; j < 8; j++) {
        int d = h*64 + j*8 + qc*2;
        *(__half2*)(g_attnh + ((size_t)(bi*LL + r0))*DMODEL + d) =
            __floats2half2_rn(o[j][0]*inv0, o[j][1]*inv0);
        *(__half2*)(g_attnh + ((size_t)(bi*LL + r1))*DMODEL + d) =
            __floats2half2_rn(o[j][2]*inv1, o[j][3]*inv1);
    }
}

// ---------------------------------------------------------------------------
extern "C" void kernel_launch(void* const* d_in, const int* in_sizes, int n_in,
                              void* d_out, int out_size)
{
    const float* q  = (const float*)d_in[0];
    const float* k  = (const float*)d_in[1];
    const float* v  = (const float*)d_in[2];
    const float* tm = (const float*)d_in[3];
    const float* am = (const float*)d_in[4];
    const float* wq = (const float*)d_in[6];
    const float* bq = (const float*)d_in[7];
    const float* wk = (const float*)d_in[8];
    const float* bk = (const float*)d_in[9];
    const float* wv = (const float*)d_in[10];
    const float* bv = (const float*)d_in[11];
    const float* wo = (const float*)d_in[12];
    const float* bo = (const float*)d_in[13];
    float* out = (float*)d_out;

    __half *xq, *xk, *xv, *wh, *gq, *gk, *gv, *gattn;
    float *gcoef;
    cudaGetSymbolAddress((void**)&xq,    g_xq);
    cudaGetSymbolAddress((void**)&xk,    g_xk);
    cudaGetSymbolAddress((void**)&xv,    g_xv);
    cudaGetSymbolAddress((void**)&wh,    g_wh);
    cudaGetSymbolAddress((void**)&gq,    g_qh);
    cudaGetSymbolAddress((void**)&gk,    g_kh);
    cudaGetSymbolAddress((void**)&gv,    g_vh);
    cudaGetSymbolAddress((void**)&gattn, g_attnh);
    cudaGetSymbolAddress((void**)&gcoef, g_coef);

    cudaFuncSetAttribute(gemm_qkv, cudaFuncAttributeMaxDynamicSharedMemorySize, GEMM_SMEM);
    cudaFuncSetAttribute(gemm_out, cudaFuncAttributeMaxDynamicSharedMemorySize, GEMM_SMEM);
    cudaFuncSetAttribute(attn_kernel, cudaFuncAttributeMaxDynamicSharedMemorySize, ATTN_SMEM);

    const int NBIG = BB*LL*DMODEL/4;
    const int NW   = WSZ/4;
    CvtArgs ca;
    ca.src[0] = q;  ca.dst[0] = xq;         ca.n4[0] = NBIG;
    ca.src[1] = k;  ca.dst[1] = xk;         ca.n4[1] = NBIG;
    ca.src[2] = v;  ca.dst[2] = xv;         ca.n4[2] = NBIG;
    ca.src[3] = wq; ca.dst[3] = wh;         ca.n4[3] = NW;
    ca.src[4] = wk; ca.dst[4] = wh + WSZ;   ca.n4[4] = NW;
    ca.src[5] = wv; ca.dst[5] = wh + 2*WSZ; ca.n4[5] = NW;
    ca.src[6] = wo; ca.dst[6] = wh + 3*WSZ; ca.n4[6] = NW;
    cvt_kernel<<<dim3(256, 7), 256>>>(ca);

    coef_kernel<<<2, 1024>>>(tm, am);

    QkvArgs qkv;
    qkv.X[0] = xq; qkv.X[1] = xk; qkv.X[2] = xv;
    qkv.W[0] = wh; qkv.W[1] = wh + WSZ; qkv.W[2] = wh + 2*WSZ;
    qkv.bias[0] = bq; qkv.bias[1] = bk; qkv.bias[2] = bv;
    qkv.Y[0] = gq; qkv.Y[1] = gk; qkv.Y[2] = gv;
    qkv.mode[0] = 1; qkv.mode[1] = 2; qkv.mode[2] = 3;
    qkv.coef = gcoef;
    gemm_qkv<<<dim3(8, 32, 3), 256, GEMM_SMEM>>>(qkv);

    attn_kernel<<<dim3(16, 16), 256, ATTN_SMEM>>>();

    gemm_out<<<dim3(8, 32), 256, GEMM_SMEM>>>(gattn, wh + 3*WSZ, bo, out);
}

// round 10
// speedup vs baseline: 1.1588x; 1.0244x over previous
#include <cuda_runtime.h>
#include <cuda_fp16.h>
#include <cstdint>

#define BB     2
#define LL     2048
#define LTXT   1024
#define DMODEL 512
#define NHEAD  8
#define DHEAD  64
#define WSZ    (DMODEL*DMODEL)

// Scratch (device globals; no allocations allowed)
__device__ __half g_xq[BB*LL*DMODEL];
__device__ __half g_xk[BB*LL*DMODEL];
__device__ __half g_xv[BB*LL*DMODEL];
__device__ __half g_wh[4*WSZ];
__device__ __half g_qh[BB*NHEAD*LL*DHEAD];    // [bh][l][d], pre-scaled log2e/8
__device__ __half g_kh[BB*NHEAD*LL*DHEAD];    // [bh][l][d]
__device__ __half g_vh[BB*NHEAD*LL*DHEAD];    // TRANSPOSED [bh][d][l], pre-mul coef
__device__ __half g_attnh[BB*LL*DMODEL];      // [l][512]
__device__ float  g_coef[BB*LL];
__device__ float  g_kbias[BB*LL];             // 0 (unmasked) or -30000 (masked)

// ---------------------------------------------------------------------------
// Helpers
// ---------------------------------------------------------------------------
__device__ __forceinline__ uint32_t pk(float lo, float hi) {
    __half2 h = __floats2half2_rn(lo, hi);
    return *reinterpret_cast<uint32_t*>(&h);
}
__device__ __forceinline__ float ex2(float x) {
    float r;
    asm("ex2.approx.f32 %0, %1;" : "=f"(r) : "f"(x));
    return r;
}
__device__ __forceinline__ void mma16(float* c,
    uint32_t a0, uint32_t a1, uint32_t a2, uint32_t a3,
    uint32_t b0, uint32_t b1)
{
    asm("mma.sync.aligned.m16n8k16.row.col.f32.f16.f16.f32 "
        "{%0,%1,%2,%3},{%4,%5,%6,%7},{%8,%9},{%0,%1,%2,%3};"
        : "+f"(c[0]), "+f"(c[1]), "+f"(c[2]), "+f"(c[3])
        : "r"(a0), "r"(a1), "r"(a2), "r"(a3), "r"(b0), "r"(b1));
}
__device__ __forceinline__ void ldsm4(uint32_t& r0, uint32_t& r1,
                                      uint32_t& r2, uint32_t& r3, uint32_t addr)
{
    asm volatile("ldmatrix.sync.aligned.m8n8.x4.shared.b16 {%0,%1,%2,%3}, [%4];"
        : "=r"(r0), "=r"(r1), "=r"(r2), "=r"(r3) : "r"(addr));
}
__device__ __forceinline__ void cp_async16(uint32_t saddr, const void* gptr) {
    asm volatile("cp.async.cg.shared.global [%0], [%1], 16;" :: "r"(saddr), "l"(gptr));
}
__device__ __forceinline__ void cp_commit() {
    asm volatile("cp.async.commit_group;");
}

// ---------------------------------------------------------------------------
// fp32 -> fp16 bulk convert (7 tensors)
// ---------------------------------------------------------------------------
struct CvtArgs {
    const float* src[7];
    __half*      dst[7];
    int          n4[7];
};

__global__ void __launch_bounds__(256) cvt_kernel(CvtArgs a)
{
    const int z = blockIdx.y;
    const float4* s = (const float4*)a.src[z];
    uint2* d = (uint2*)a.dst[z];
    const int n4 = a.n4[z];
    for (int i = blockIdx.x*256 + threadIdx.x; i < n4; i += gridDim.x*256) {
        float4 v = s[i];
        d[i] = make_uint2(pk(v.x, v.y), pk(v.z, v.w));
    }
}

// ---------------------------------------------------------------------------
// Mask -> coef (post-softmax weight; 0 iff masked) + additive key bias.
// ---------------------------------------------------------------------------
__global__ void coef_kernel(const float* __restrict__ tm, const float* __restrict__ am)
{
    int b = blockIdx.x;
    int t = threadIdx.x;
    float tv = tm[b*LTXT + t];
    float av = am[b*LTXT + t];
    float ts = tv, as_ = av;
    #pragma unroll
    for (int o = 16; o; o >>= 1) {
        ts  += __shfl_xor_sync(0xffffffffu, ts,  o);
        as_ += __shfl_xor_sync(0xffffffffu, as_, o);
    }
    __shared__ float st[32], sa[32];
    int warp = t >> 5, lane = t & 31;
    if (lane == 0) { st[warp] = ts; sa[warp] = as_; }
    __syncthreads();
    if (warp == 0) {
        ts = st[lane]; as_ = sa[lane];
        #pragma unroll
        for (int o = 16; o; o >>= 1) {
            ts  += __shfl_xor_sync(0xffffffffu, ts,  o);
            as_ += __shfl_xor_sync(0xffffffffu, as_, o);
        }
        if (lane == 0) { st[0] = ts; sa[0] = as_; }
    }
    __syncthreads();
    float tsum = st[0], asum = sa[0], tot = tsum + asum;
    g_coef[b*LL + t]         = tv * (tot / (2.0f * tsum));
    g_coef[b*LL + LTXT + t]  = av * (tot / (2.0f * asum));
    g_kbias[b*LL + t]        = (tv == 0.0f) ? -30000.0f : 0.0f;
    g_kbias[b*LL + LTXT + t] = (av == 0.0f) ? -30000.0f : 0.0f;
}

// ---------------------------------------------------------------------------
// FP16 TC GEMM, 3-stage cp.async, BK=64, ldmatrix.x4 fragment loads.
// ---------------------------------------------------------------------------
#define GAP 36
#define XST (128*GAP)
#define WST (64*GAP)
#define GEMM_SMEM (3*(XST + WST)*4)
#define NKC (DMODEL/64)

struct QkvArgs {
    const __half* X[3];
    const __half* W[3];
    const float*  bias[3];
    __half*       Y[3];
    int           mode[3];
    const float*  coef;
};

template<typename EPI>
__device__ __forceinline__ void gemm_core(
    const __half* __restrict__ X, const __half* __restrict__ W,
    uint32_t* smem, int m0, int n0, EPI epi)
{
    uint32_t* sX = smem;
    uint32_t* sW = smem + 3*XST;

    const int tid  = threadIdx.x;
    const int warp = tid >> 5, lane = tid & 31;
    const int wm = (warp >> 1) * 32;
    const int wn = (warp & 1) * 32;
    const int rowin = lane & 7;
    const int selh  = lane >> 4;
    const int sell  = (lane >> 3) & 1;

    const uint32_t bX = (uint32_t)__cvta_generic_to_shared(sX);
    const uint32_t bW = (uint32_t)__cvta_generic_to_shared(sW);

    auto prefetch = [&](int buf, int k0) {
        #pragma unroll
        for (int i = 0; i < 4; i++) {
            int s = tid + i*256;
            int r = s >> 3, ch = s & 7;
            cp_async16(bX + (buf*XST + r*GAP + ch*4)*4,
                       X + (size_t)(m0 + r)*DMODEL + k0 + ch*8);
        }
        #pragma unroll
        for (int i = 0; i < 2; i++) {
            int s = tid + i*256;
            int r = s >> 3, ch = s & 7;
            cp_async16(bW + (buf*WST + r*GAP + ch*4)*4,
                       W + (size_t)(n0 + r)*DMODEL + k0 + ch*8);
        }
        cp_commit();
    };

    const uint32_t xoff = ((wm + sell*8 + rowin)*GAP + selh*4)*4;
    const uint32_t woff = ((wn + selh*8 + rowin)*GAP + sell*4)*4;

    float c[2][4][4] = {};

    prefetch(0, 0);
    prefetch(1, 64);
    #pragma unroll 1
    for (int kc = 0; kc < NKC; kc++) {
        if (kc + 1 < NKC) asm volatile("cp.async.wait_group 1;");
        else              asm volatile("cp.async.wait_group 0;");
        __syncthreads();
        if (kc + 2 < NKC) prefetch((kc+2)%3, (kc+2)*64);

        const uint32_t xb = bX + (kc%3)*XST*4 + xoff;
        const uint32_t wb = bW + (kc%3)*WST*4 + woff;
        #pragma unroll
        for (int kk = 0; kk < 4; kk++) {
            uint32_t a[2][4];
            ldsm4(a[0][0], a[0][1], a[0][2], a[0][3], xb + kk*32);
            ldsm4(a[1][0], a[1][1], a[1][2], a[1][3], xb + 16*GAP*4 + kk*32);
            #pragma unroll
            for (int njp = 0; njp < 2; njp++) {
                uint32_t b0, b1, b2, b3;
                ldsm4(b0, b1, b2, b3, wb + njp*16*GAP*4 + kk*32);
                mma16(c[0][2*njp  ], a[0][0], a[0][1], a[0][2], a[0][3], b0, b1);
                mma16(c[1][2*njp  ], a[1][0], a[1][1], a[1][2], a[1][3], b0, b1);
                mma16(c[0][2*njp+1], a[0][0], a[0][1], a[0][2], a[0][3], b2, b3);
                mma16(c[1][2*njp+1], a[1][0], a[1][1], a[1][2], a[1][3], b2, b3);
            }
        }
    }

    const int qr = lane >> 2, qc = lane & 3;
    #pragma unroll
    for (int mi = 0; mi < 2; mi++) {
        int row0 = m0 + wm + mi*16 + qr;
        #pragma unroll
        for (int nj = 0; nj < 4; nj++) {
            int col = n0 + wn + nj*8 + qc*2;
            epi(row0, col, c[mi][nj]);
        }
    }
}

__global__ void __launch_bounds__(256) gemm_qkv(QkvArgs args)
{
    extern __shared__ uint32_t smg[];
    const int z = blockIdx.z;
    const float* B = args.bias[z];
    __half* Y = args.Y[z];
    const int mode = args.mode[z];
    const float* coef = args.coef;

    gemm_core(args.X[z], args.W[z], smg, blockIdx.y*128, blockIdx.x*64,
        [&](int row0, int col, float* cc) {
            int row1 = row0 + 8;
            float b0 = B[col], b1 = B[col+1];
            float v00 = cc[0] + b0, v01 = cc[1] + b1;
            float v10 = cc[2] + b0, v11 = cc[3] + b1;
            int h = col >> 6, d = col & 63;
            int bi0 = row0 >> 11, l0 = row0 & 2047;
            int bi1 = row1 >> 11, l1 = row1 & 2047;
            if (mode == 1) {          // Q: 1/8 * log2(e)  (log2-domain softmax)
                const float qs = 0.125f * 1.44269504f;
                v00 *= qs; v01 *= qs; v10 *= qs; v11 *= qs;
            }
            if (mode == 3) {
                float c0 = coef[row0], c1 = coef[row1];
                __half* p = Y + ((size_t)(bi0*NHEAD + h)*DHEAD + d)*LL;  // [bh][d][l]
                p[l0]      = __float2half(v00*c0);
                p[LL + l0] = __float2half(v01*c0);
                p[l1]      = __float2half(v10*c1);
                p[LL + l1] = __float2half(v11*c1);
            } else {
                *(__half2*)(Y + ((size_t)(bi0*NHEAD + h)*LL + l0)*DHEAD + d) =
                    __floats2half2_rn(v00, v01);
                *(__half2*)(Y + ((size_t)(bi1*NHEAD + h)*LL + l1)*DHEAD + d) =
                    __floats2half2_rn(v10, v11);
            }
        });
}

__global__ void __launch_bounds__(256) gemm_out(
    const __half* __restrict__ Xh, const __half* __restrict__ Wh,
    const float* __restrict__ B, float* __restrict__ Y)
{
    extern __shared__ uint32_t smg[];
    gemm_core(Xh, Wh, smg, blockIdx.y*128, blockIdx.x*64,
        [&](int row0, int col, float* cc) {
            float b0 = B[col], b1 = B[col+1];
            *(float2*)(Y + (size_t)row0*DMODEL + col)     = make_float2(cc[0]+b0, cc[1]+b1);
            *(float2*)(Y + (size_t)(row0+8)*DMODEL + col) = make_float2(cc[2]+b0, cc[3]+b1);
        });
}

// ---------------------------------------------------------------------------
// Fused attention: fp16 m16n8k16 + ldmatrix.x4, log2-domain softmax.
// BM=128, BN=64, 256 threads, 2 CTAs/SM.  Additive k-mask, rescale-skip vote.
// ---------------------------------------------------------------------------
#define AP 36
#define KT (64*AP)
#define ATTN_SMEM ((6*KT + 3*64) * 4)
#define NT (LL/64)

__global__ void __launch_bounds__(256, 2) attn_kernel()
{
    extern __shared__ uint32_t smu[];
    uint32_t* Ks  = smu;                    // [3][64key][AP]
    uint32_t* Vs  = smu + 3*KT;             // [3][64d][AP]  (V^T)
    float*    kbs = (float*)(smu + 6*KT);   // [3][64] additive key bias

    const int tid  = threadIdx.x;
    const int warp = tid >> 5, lane = tid & 31;
    const int qr = lane >> 2, qc = lane & 3;
    const int bh = blockIdx.y, bi = bh >> 3, h = bh & 7;
    const int q0 = blockIdx.x * 128;
    const int wrow = warp * 16;
    const int rowin = lane & 7;
    const int selh  = lane >> 4;
    const int sell  = (lane >> 3) & 1;

    const __half* kbase = g_kh + (size_t)bh * LL * DHEAD;
    const __half* vbase = g_vh + (size_t)bh * DHEAD * LL;
    const float*  cbase = g_coef + bi*LL;
    const float*  bbase = g_kbias + bi*LL;

    const uint32_t sK = (uint32_t)__cvta_generic_to_shared(Ks);
    const uint32_t sV = (uint32_t)__cvta_generic_to_shared(Vs);
    const uint32_t sC = (uint32_t)__cvta_generic_to_shared(kbs);

    auto prefetch = [&](int buf, int k0) {
        #pragma unroll
        for (int i = 0; i < 2; i++) {
            int s = tid + i*256;
            int r = s >> 3, ch = s & 7;
            cp_async16(sK + (buf*KT + r*AP + ch*4)*4,
                       kbase + (size_t)(k0 + r)*DHEAD + ch*8);
            cp_async16(sV + (buf*KT + r*AP + ch*4)*4,
                       vbase + (size_t)r*LL + k0 + ch*8);
        }
        if (tid < 16)
            cp_async16(sC + (buf*64 + tid*4)*4, bbase + k0 + tid*4);
        cp_commit();
    };

    prefetch(0, 0);
    prefetch(1, 64);

    // ---- Q fragments straight from gmem (fp16, pre-scaled log2e/8) ----
    const uint32_t* qrow0 =
        (const uint32_t*)(g_qh + ((size_t)bh*LL + q0 + wrow + qr)*DHEAD);
    const uint32_t* qrow1 = qrow0 + 8*(DHEAD/2);
    uint32_t aQ[4][4];
    #pragma unroll
    for (int kk = 0; kk < 4; kk++) {
        aQ[kk][0] = qrow0[kk*8 + qc];
        aQ[kk][1] = qrow1[kk*8 + qc];
        aQ[kk][2] = qrow0[kk*8 + qc + 4];
        aQ[kk][3] = qrow1[kk*8 + qc + 4];
    }
    const bool q0ok = (cbase[q0 + wrow + qr]     != 0.0f);
    const bool q1ok = (cbase[q0 + wrow + qr + 8] != 0.0f);

    const uint32_t fragoff = (((selh*8 + rowin)*AP) + sell*4)*4;

    float o[8][4] = {};
    float m0 = -1e30f, m1 = -1e30f, l0 = 0.0f, l1 = 0.0f;
    int buf = 0;

    #pragma unroll 1
    for (int t = 0; t < NT; t++) {
        if (t + 1 < NT) asm volatile("cp.async.wait_group 1;");
        else            asm volatile("cp.async.wait_group 0;");
        __syncthreads();
        if (t + 2 < NT) {
            int nb = buf + 2; if (nb >= 3) nb -= 3;
            prefetch(nb, (t+2)*64);
        }

        const uint32_t kb_a = sK + buf*KT*4 + fragoff;
        const uint32_t vb_a = sV + buf*KT*4 + fragoff;
        const float*   kb   = kbs + buf*64;
        buf++; if (buf == 3) buf = 0;

        // ---- S = (Q·log2e/8) @ K^T ----
        float s[8][4] = {};
        #pragma unroll
        for (int kk = 0; kk < 4; kk++) {
            #pragma unroll
            for (int jp = 0; jp < 4; jp++) {
                uint32_t b0, b1, b2, b3;
                ldsm4(b0, b1, b2, b3, kb_a + (jp*16*AP)*4 + kk*32);
                mma16(s[2*jp  ], aQ[kk][0], aQ[kk][1], aQ[kk][2], aQ[kk][3], b0, b1);
                mma16(s[2*jp+1], aQ[kk][0], aQ[kk][1], aQ[kk][2], aQ[kk][3], b2, b3);
            }
        }

        // ---- additive k-mask; q-masked rows -> 0 (uniform softmax) ----
        #pragma unroll
        for (int j = 0; j < 8; j++) {
            float2 kbv = *(const float2*)(kb + j*8 + qc*2);
            s[j][0] += kbv.x; s[j][1] += kbv.y;
            s[j][2] += kbv.x; s[j][3] += kbv.y;
        }
        if (!q0ok) {
            #pragma unroll
            for (int j = 0; j < 8; j++) { s[j][0] = 0.0f; s[j][1] = 0.0f; }
        }
        if (!q1ok) {
            #pragma unroll
            for (int j = 0; j < 8; j++) { s[j][2] = 0.0f; s[j][3] = 0.0f; }
        }

        // ---- online softmax (log2 domain) ----
        float mx0 = -1e30f, mx1 = -1e30f;
        #pragma unroll
        for (int j = 0; j < 8; j++) {
            mx0 = fmaxf(mx0, fmaxf(s[j][0], s[j][1]));
            mx1 = fmaxf(mx1, fmaxf(s[j][2], s[j][3]));
        }
        mx0 = fmaxf(mx0, __shfl_xor_sync(0xffffffffu, mx0, 1));
        mx0 = fmaxf(mx0, __shfl_xor_sync(0xffffffffu, mx0, 2));
        mx1 = fmaxf(mx1, __shfl_xor_sync(0xffffffffu, mx1, 1));
        mx1 = fmaxf(mx1, __shfl_xor_sync(0xffffffffu, mx1, 2));

        if (__any_sync(0xffffffffu, (mx0 > m0) | (mx1 > m1))) {
            float nm0 = fmaxf(m0, mx0), nm1 = fmaxf(m1, mx1);
            float sc0 = ex2(m0 - nm0), sc1 = ex2(m1 - nm1);
            #pragma unroll
            for (int j = 0; j < 8; j++) {
                o[j][0] *= sc0; o[j][1] *= sc0;
                o[j][2] *= sc1; o[j][3] *= sc1;
            }
            l0 *= sc0; l1 *= sc1;
            m0 = nm0;  m1 = nm1;
        }

        // ---- exp2 -> fp16 A-fragments -> PV mma ----
        float rs0 = 0.0f, rs1 = 0.0f;
        #pragma unroll
        for (int jj = 0; jj < 4; jj++) {
            float p00 = ex2(s[2*jj  ][0] - m0);
            float p01 = ex2(s[2*jj  ][1] - m0);
            float p02 = ex2(s[2*jj  ][2] - m1);
            float p03 = ex2(s[2*jj  ][3] - m1);
            float p10 = ex2(s[2*jj+1][0] - m0);
            float p11 = ex2(s[2*jj+1][1] - m0);
            float p12 = ex2(s[2*jj+1][2] - m1);
            float p13 = ex2(s[2*jj+1][3] - m1);
            rs0 += p00 + p01 + p10 + p11;
            rs1 += p02 + p03 + p12 + p13;

            uint32_t a0 = pk(p00, p01);
            uint32_t a1 = pk(p02, p03);
            uint32_t a2 = pk(p10, p11);
            uint32_t a3 = pk(p12, p13);

            #pragma unroll
            for (int njp = 0; njp < 4; njp++) {
                uint32_t b0, b1, b2, b3;
                ldsm4(b0, b1, b2, b3, vb_a + (njp*16*AP)*4 + jj*32);
                mma16(o[2*njp  ], a0, a1, a2, a3, b0, b1);
                mma16(o[2*njp+1], a0, a1, a2, a3, b2, b3);
            }
        }
        rs0 += __shfl_xor_sync(0xffffffffu, rs0, 1);
        rs0 += __shfl_xor_sync(0xffffffffu, rs0, 2);
        rs1 += __shfl_xor_sync(0xffffffffu, rs1, 1);
        rs1 += __shfl_xor_sync(0xffffffffu, rs1, 2);
        l0 += rs0;
        l1 += rs1;
    }

    // ---- epilogue ----
    float inv0 = 1.0f / l0, inv1 = 1.0f / l1;
    int r0 = q0 + wrow + qr, r1 = r0 + 8;
    #pragma unroll
    for (int j = 0; j < 8; j++) {
        int d = h*64 + j*8 + qc*2;
        *(__half2*)(g_attnh + ((size_t)(bi*LL + r0))*DMODEL + d) =
            __floats2half2_rn(o[j][0]*inv0, o[j][1]*inv0);
        *(__half2*)(g_attnh + ((size_t)(bi*LL + r1))*DMODEL + d) =
            __floats2half2_rn(o[j][2]*inv1, o[j][3]*inv1);
    }
}

// ---------------------------------------------------------------------------
extern "C" void kernel_launch(void* const* d_in, const int* in_sizes, int n_in,
                              void* d_out, int out_size)
{
    const float* q  = (const float*)d_in[0];
    const float* k  = (const float*)d_in[1];
    const float* v  = (const float*)d_in[2];
    const float* tm = (const float*)d_in[3];
    const float* am = (const float*)d_in[4];
    const float* wq = (const float*)d_in[6];
    const float* bq = (const float*)d_in[7];
    const float* wk = (const float*)d_in[8];
    const float* bk = (const float*)d_in[9];
    const float* wv = (const float*)d_in[10];
    const float* bv = (const float*)d_in[11];
    const float* wo = (const float*)d_in[12];
    const float* bo = (const float*)d_in[13];
    float* out = (float*)d_out;

    __half *xq, *xk, *xv, *wh, *gq, *gk, *gv, *gattn;
    float *gcoef;
    cudaGetSymbolAddress((void**)&xq,    g_xq);
    cudaGetSymbolAddress((void**)&xk,    g_xk);
    cudaGetSymbolAddress((void**)&xv,    g_xv);
    cudaGetSymbolAddress((void**)&wh,    g_wh);
    cudaGetSymbolAddress((void**)&gq,    g_qh);
    cudaGetSymbolAddress((void**)&gk,    g_kh);
    cudaGetSymbolAddress((void**)&gv,    g_vh);
    cudaGetSymbolAddress((void**)&gattn, g_attnh);
    cudaGetSymbolAddress((void**)&gcoef, g_coef);

    cudaFuncSetAttribute(gemm_qkv, cudaFuncAttributeMaxDynamicSharedMemorySize, GEMM_SMEM);
    cudaFuncSetAttribute(gemm_out, cudaFuncAttributeMaxDynamicSharedMemorySize, GEMM_SMEM);
    cudaFuncSetAttribute(attn_kernel, cudaFuncAttributeMaxDynamicSharedMemorySize, ATTN_SMEM);

    const int NBIG = BB*LL*DMODEL/4;
    const int NW   = WSZ/4;
    CvtArgs ca;
    ca.src[0] = q;  ca.dst[0] = xq;         ca.n4[0] = NBIG;
    ca.src[1] = k;  ca.dst[1] = xk;         ca.n4[1] = NBIG;
    ca.src[2] = v;  ca.dst[2] = xv;         ca.n4[2] = NBIG;
    ca.src[3] = wq; ca.dst[3] = wh;         ca.n4[3] = NW;
    ca.src[4] = wk; ca.dst[4] = wh + WSZ;   ca.n4[4] = NW;
    ca.src[5] = wv; ca.dst[5] = wh + 2*WSZ; ca.n4[5] = NW;
    ca.src[6] = wo; ca.dst[6] = wh + 3*WSZ; ca.n4[6] = NW;
    cvt_kernel<<<dim3(256, 7), 256>>>(ca);

    coef_kernel<<<2, 1024>>>(tm, am);

    QkvArgs qkv;
    qkv.X[0] = xq; qkv.X[1] = xk; qkv.X[2] = xv;
    qkv.W[0] = wh; qkv.W[1] = wh + WSZ; qkv.W[2] = wh + 2*WSZ;
    qkv.bias[0] = bq; qkv.bias[1] = bk; qkv.bias[2] = bv;
    qkv.Y[0] = gq; qkv.Y[1] = gk; qkv.Y[2] = gv;
    qkv.mode[0] = 1; qkv.mode[1] = 2; qkv.mode[2] = 3;
    qkv.coef = gcoef;
    gemm_qkv<<<dim3(8, 32, 3), 256, GEMM_SMEM>>>(qkv);

    attn_kernel<<<dim3(16, 16), 256, ATTN_SMEM>>>();

    gemm_out<<<dim3(8, 32), 256, GEMM_SMEM>>>(gattn, wh + 3*WSZ, bo, out);
}

// round 12
// speedup vs baseline: 1.2132x; 1.0469x over previous
#include <cuda_runtime.h>
#include <cuda_fp16.h>
#include <cstdint>

#define BB     2
#define LL     2048
#define LTXT   1024
#define DMODEL 512
#define NHEAD  8
#define DHEAD  64
#define WSZ    (DMODEL*DMODEL)

// Scratch (device globals; no allocations allowed)
__device__ __half g_xq[BB*LL*DMODEL];
__device__ __half g_xk[BB*LL*DMODEL];
__device__ __half g_xv[BB*LL*DMODEL];
__device__ __half g_wh[4*WSZ];
__device__ __half g_qh[BB*NHEAD*LL*DHEAD];    // [bh][l][d], pre-scaled log2e/8
__device__ __half g_kh[BB*NHEAD*LL*DHEAD];    // [bh][l][d]
__device__ __half g_vh[BB*NHEAD*LL*DHEAD];    // TRANSPOSED [bh][d][l], pre-mul coef
__device__ __half g_attnh[BB*LL*DMODEL];      // [l][512]
__device__ float  g_coef[BB*LL];
__device__ __half g_kmulh[BB*LL];             // 1.0 (unmasked) or 0.0 (masked)

// ---------------------------------------------------------------------------
// Helpers
// ---------------------------------------------------------------------------
__device__ __forceinline__ uint32_t pk(float lo, float hi) {
    __half2 h = __floats2half2_rn(lo, hi);
    return *reinterpret_cast<uint32_t*>(&h);
}
__device__ __forceinline__ uint32_t pkcvt(float lo, float hi) {
    uint32_t r;
    asm("cvt.rn.f16x2.f32 %0, %1, %2;" : "=r"(r) : "f"(hi), "f"(lo));
    return r;
}
__device__ __forceinline__ uint32_t h2ex2(uint32_t x) {
    uint32_t r;
    asm("ex2.approx.f16x2 %0, %1;" : "=r"(r) : "r"(x));
    return r;
}
__device__ __forceinline__ uint32_t h2mul(uint32_t a, uint32_t b) {
    uint32_t r;
    asm("mul.f16x2 %0, %1, %2;" : "=r"(r) : "r"(a), "r"(b));
    return r;
}
__device__ __forceinline__ float ex2(float x) {
    float r;
    asm("ex2.approx.f32 %0, %1;" : "=f"(r) : "f"(x));
    return r;
}
__device__ __forceinline__ void mma16(float* c,
    uint32_t a0, uint32_t a1, uint32_t a2, uint32_t a3,
    uint32_t b0, uint32_t b1)
{
    asm("mma.sync.aligned.m16n8k16.row.col.f32.f16.f16.f32 "
        "{%0,%1,%2,%3},{%4,%5,%6,%7},{%8,%9},{%0,%1,%2,%3};"
        : "+f"(c[0]), "+f"(c[1]), "+f"(c[2]), "+f"(c[3])
        : "r"(a0), "r"(a1), "r"(a2), "r"(a3), "r"(b0), "r"(b1));
}
__device__ __forceinline__ void ldsm4(uint32_t& r0, uint32_t& r1,
                                      uint32_t& r2, uint32_t& r3, uint32_t addr)
{
    asm volatile("ldmatrix.sync.aligned.m8n8.x4.shared.b16 {%0,%1,%2,%3}, [%4];"
        : "=r"(r0), "=r"(r1), "=r"(r2), "=r"(r3) : "r"(addr));
}
__device__ __forceinline__ void cp_async16(uint32_t saddr, const void* gptr) {
    asm volatile("cp.async.cg.shared.global [%0], [%1], 16;" :: "r"(saddr), "l"(gptr));
}
__device__ __forceinline__ void cp_commit() {
    asm volatile("cp.async.commit_group;");
}

// ---------------------------------------------------------------------------
// fp32 -> fp16 bulk convert (7 tensors)
// ---------------------------------------------------------------------------
struct CvtArgs {
    const float* src[7];
    __half*      dst[7];
    int          n4[7];
};

__global__ void __launch_bounds__(256) cvt_kernel(CvtArgs a)
{
    const int z = blockIdx.y;
    const float4* s = (const float4*)a.src[z];
    uint2* d = (uint2*)a.dst[z];
    const int n4 = a.n4[z];
    for (int i = blockIdx.x*256 + threadIdx.x; i < n4; i += gridDim.x*256) {
        float4 v = s[i];
        d[i] = make_uint2(pk(v.x, v.y), pk(v.z, v.w));
    }
}

// ---------------------------------------------------------------------------
// Mask -> coef (post-softmax weight; 0 iff masked) + multiplicative key mask.
// ---------------------------------------------------------------------------
__global__ void coef_kernel(const float* __restrict__ tm, const float* __restrict__ am)
{
    int b = blockIdx.x;
    int t = threadIdx.x;
    float tv = tm[b*LTXT + t];
    float av = am[b*LTXT + t];
    float ts = tv, as_ = av;
    #pragma unroll
    for (int o = 16; o; o >>= 1) {
        ts  += __shfl_xor_sync(0xffffffffu, ts,  o);
        as_ += __shfl_xor_sync(0xffffffffu, as_, o);
    }
    __shared__ float st[32], sa[32];
    int warp = t >> 5, lane = t & 31;
    if (lane == 0) { st[warp] = ts; sa[warp] = as_; }
    __syncthreads();
    if (warp == 0) {
        ts = st[lane]; as_ = sa[lane];
        #pragma unroll
        for (int o = 16; o; o >>= 1) {
            ts  += __shfl_xor_sync(0xffffffffu, ts,  o);
            as_ += __shfl_xor_sync(0xffffffffu, as_, o);
        }
        if (lane == 0) { st[0] = ts; sa[0] = as_; }
    }
    __syncthreads();
    float tsum = st[0], asum = sa[0], tot = tsum + asum;
    g_coef[b*LL + t]         = tv * (tot / (2.0f * tsum));
    g_coef[b*LL + LTXT + t]  = av * (tot / (2.0f * asum));
    g_kmulh[b*LL + t]        = __float2half(tv == 0.0f ? 0.0f : 1.0f);
    g_kmulh[b*LL + LTXT + t] = __float2half(av == 0.0f ? 0.0f : 1.0f);
}

// ---------------------------------------------------------------------------
// FP16 TC GEMM, 3-stage cp.async, BK=64, ldmatrix.x4 fragment loads.
// ---------------------------------------------------------------------------
#define GAP 36
#define XST (128*GAP)
#define WST (64*GAP)
#define GEMM_SMEM (3*(XST + WST)*4)
#define NKC (DMODEL/64)

struct QkvArgs {
    const __half* X[3];
    const __half* W[3];
    const float*  bias[3];
    __half*       Y[3];
    int           mode[3];
    const float*  coef;
};

template<typename EPI>
__device__ __forceinline__ void gemm_core(
    const __half* __restrict__ X, const __half* __restrict__ W,
    uint32_t* smem, int m0, int n0, EPI epi)
{
    uint32_t* sX = smem;
    uint32_t* sW = smem + 3*XST;

    const int tid  = threadIdx.x;
    const int warp = tid >> 5, lane = tid & 31;
    const int wm = (warp >> 1) * 32;
    const int wn = (warp & 1) * 32;
    const int rowin = lane & 7;
    const int selh  = lane >> 4;
    const int sell  = (lane >> 3) & 1;

    const uint32_t bX = (uint32_t)__cvta_generic_to_shared(sX);
    const uint32_t bW = (uint32_t)__cvta_generic_to_shared(sW);

    auto prefetch = [&](int buf, int k0) {
        #pragma unroll
        for (int i = 0; i < 4; i++) {
            int s = tid + i*256;
            int r = s >> 3, ch = s & 7;
            cp_async16(bX + (buf*XST + r*GAP + ch*4)*4,
                       X + (size_t)(m0 + r)*DMODEL + k0 + ch*8);
        }
        #pragma unroll
        for (int i = 0; i < 2; i++) {
            int s = tid + i*256;
            int r = s >> 3, ch = s & 7;
            cp_async16(bW + (buf*WST + r*GAP + ch*4)*4,
                       W + (size_t)(n0 + r)*DMODEL + k0 + ch*8);
        }
        cp_commit();
    };

    const uint32_t xoff = ((wm + sell*8 + rowin)*GAP + selh*4)*4;
    const uint32_t woff = ((wn + selh*8 + rowin)*GAP + sell*4)*4;

    float c[2][4][4] = {};

    prefetch(0, 0);
    prefetch(1, 64);
    #pragma unroll 1
    for (int kc = 0; kc < NKC; kc++) {
        if (kc + 1 < NKC) asm volatile("cp.async.wait_group 1;");
        else              asm volatile("cp.async.wait_group 0;");
        __syncthreads();
        if (kc + 2 < NKC) prefetch((kc+2)%3, (kc+2)*64);

        const uint32_t xb = bX + (kc%3)*XST*4 + xoff;
        const uint32_t wb = bW + (kc%3)*WST*4 + woff;
        #pragma unroll
        for (int kk = 0; kk < 4; kk++) {
            uint32_t a[2][4];
            ldsm4(a[0][0], a[0][1], a[0][2], a[0][3], xb + kk*32);
            ldsm4(a[1][0], a[1][1], a[1][2], a[1][3], xb + 16*GAP*4 + kk*32);
            #pragma unroll
            for (int njp = 0; njp < 2; njp++) {
                uint32_t b0, b1, b2, b3;
                ldsm4(b0, b1, b2, b3, wb + njp*16*GAP*4 + kk*32);
                mma16(c[0][2*njp  ], a[0][0], a[0][1], a[0][2], a[0][3], b0, b1);
                mma16(c[1][2*njp  ], a[1][0], a[1][1], a[1][2], a[1][3], b0, b1);
                mma16(c[0][2*njp+1], a[0][0], a[0][1], a[0][2], a[0][3], b2, b3);
                mma16(c[1][2*njp+1], a[1][0], a[1][1], a[1][2], a[1][3], b2, b3);
            }
        }
    }

    const int qr = lane >> 2, qc = lane & 3;
    #pragma unroll
    for (int mi = 0; mi < 2; mi++) {
        int row0 = m0 + wm + mi*16 + qr;
        #pragma unroll
        for (int nj = 0; nj < 4; nj++) {
            int col = n0 + wn + nj*8 + qc*2;
            epi(row0, col, c[mi][nj]);
        }
    }
}

__global__ void __launch_bounds__(256) gemm_qkv(QkvArgs args)
{
    extern __shared__ uint32_t smg[];
    const int z = blockIdx.z;
    const float* B = args.bias[z];
    __half* Y = args.Y[z];
    const int mode = args.mode[z];
    const float* coef = args.coef;

    gemm_core(args.X[z], args.W[z], smg, blockIdx.y*128, blockIdx.x*64,
        [&](int row0, int col, float* cc) {
            int row1 = row0 + 8;
            float b0 = B[col], b1 = B[col+1];
            float v00 = cc[0] + b0, v01 = cc[1] + b1;
            float v10 = cc[2] + b0, v11 = cc[3] + b1;
            int h = col >> 6, d = col & 63;
            int bi0 = row0 >> 11, l0 = row0 & 2047;
            int bi1 = row1 >> 11, l1 = row1 & 2047;
            if (mode == 1) {          // Q: 1/8 * log2(e)  (log2-domain softmax)
                const float qs = 0.125f * 1.44269504f;
                v00 *= qs; v01 *= qs; v10 *= qs; v11 *= qs;
            }
            if (mode == 3) {
                float c0 = coef[row0], c1 = coef[row1];
                __half* p = Y + ((size_t)(bi0*NHEAD + h)*DHEAD + d)*LL;  // [bh][d][l]
                p[l0]      = __float2half(v00*c0);
                p[LL + l0] = __float2half(v01*c0);
                p[l1]      = __float2half(v10*c1);
                p[LL + l1] = __float2half(v11*c1);
            } else {
                *(__half2*)(Y + ((size_t)(bi0*NHEAD + h)*LL + l0)*DHEAD + d) =
                    __floats2half2_rn(v00, v01);
                *(__half2*)(Y + ((size_t)(bi1*NHEAD + h)*LL + l1)*DHEAD + d) =
                    __floats2half2_rn(v10, v11);
            }
        });
}

__global__ void __launch_bounds__(256) gemm_out(
    const __half* __restrict__ Xh, const __half* __restrict__ Wh,
    const float* __restrict__ B, float* __restrict__ Y)
{
    extern __shared__ uint32_t smg[];
    gemm_core(Xh, Wh, smg, blockIdx.y*128, blockIdx.x*64,
        [&](int row0, int col, float* cc) {
            float b0 = B[col], b1 = B[col+1];
            *(float2*)(Y + (size_t)row0*DMODEL + col)     = make_float2(cc[0]+b0, cc[1]+b1);
            *(float2*)(Y + (size_t)(row0+8)*DMODEL + col) = make_float2(cc[2]+b0, cc[3]+b1);
        });
}

// ---------------------------------------------------------------------------
// Fused attention: fp16 m16n8k16 + ldmatrix.x4, log2-domain softmax.
// l computed BY mma (constant ones B-frag); multiplicative half2 key mask
// (FIXED: 32 uint32 per mask buffer); ex2 in f16x2.  BM=128, 2 CTAs/SM.
// ---------------------------------------------------------------------------
#define AP 36
#define KT (64*AP)
#define MB 32                                  // uint32 per mask buffer (64 halves)
#define ATTN_SMEM ((6*KT + 3*MB) * 4)
#define NT (LL/64)

__global__ void __launch_bounds__(256, 2) attn_kernel()
{
    extern __shared__ uint32_t smu[];
    uint32_t* Ks  = smu;                    // [3][64key][AP]
    uint32_t* Vs  = smu + 3*KT;             // [3][64d][AP]  (V^T)
    uint32_t* kms = smu + 6*KT;             // [3][MB] half2 key mask

    const int tid  = threadIdx.x;
    const int warp = tid >> 5, lane = tid & 31;
    const int qr = lane >> 2, qc = lane & 3;
    const int bh = blockIdx.y, bi = bh >> 3, h = bh & 7;
    const int q0 = blockIdx.x * 128;
    const int wrow = warp * 16;
    const int rowin = lane & 7;
    const int selh  = lane >> 4;
    const int sell  = (lane >> 3) & 1;

    const __half* kbase = g_kh + (size_t)bh * LL * DHEAD;
    const __half* vbase = g_vh + (size_t)bh * DHEAD * LL;
    const float*  cbase = g_coef + bi*LL;
    const __half* mbase = g_kmulh + bi*LL;

    const uint32_t sK = (uint32_t)__cvta_generic_to_shared(Ks);
    const uint32_t sV = (uint32_t)__cvta_generic_to_shared(Vs);
    const uint32_t sM = (uint32_t)__cvta_generic_to_shared(kms);

    auto prefetch = [&](int buf, int k0) {
        #pragma unroll
        for (int i = 0; i < 2; i++) {
            int s = tid + i*256;
            int r = s >> 3, ch = s & 7;
            cp_async16(sK + (buf*KT + r*AP + ch*4)*4,
                       kbase + (size_t)(k0 + r)*DHEAD + ch*8);
            cp_async16(sV + (buf*KT + r*AP + ch*4)*4,
                       vbase + (size_t)r*LL + k0 + ch*8);
        }
        if (tid < 8)
            cp_async16(sM + (buf*MB + tid*4)*4, mbase + k0 + tid*8);
        cp_commit();
    };

    prefetch(0, 0);
    prefetch(1, 64);

    // ---- Q fragments straight from gmem (fp16, pre-scaled log2e/8) ----
    const uint32_t* qrow0 =
        (const uint32_t*)(g_qh + ((size_t)bh*LL + q0 + wrow + qr)*DHEAD);
    const uint32_t* qrow1 = qrow0 + 8*(DHEAD/2);
    uint32_t aQ[4][4];
    #pragma unroll
    for (int kk = 0; kk < 4; kk++) {
        aQ[kk][0] = qrow0[kk*8 + qc];
        aQ[kk][1] = qrow1[kk*8 + qc];
        aQ[kk][2] = qrow0[kk*8 + qc + 4];
        aQ[kk][3] = qrow1[kk*8 + qc + 4];
    }
    const bool q0ok = (cbase[q0 + wrow + qr]     != 0.0f);
    const bool q1ok = (cbase[q0 + wrow + qr + 8] != 0.0f);

    const uint32_t fragoff = (((selh*8 + rowin)*AP) + sell*4)*4;
    const uint32_t bOnes = (qr == 0) ? 0x3C003C00u : 0u;  // ones col-0 B frag (l-mma)

    float o[8][4] = {};
    float ol[4] = {};                       // l accumulator c-frag (col0 @ qc==0)
    float m0 = -1e30f, m1 = -1e30f;
    int buf = 0;

    #pragma unroll 1
    for (int t = 0; t < NT; t++) {
        if (t + 1 < NT) asm volatile("cp.async.wait_group 1;");
        else            asm volatile("cp.async.wait_group 0;");
        __syncthreads();
        if (t + 2 < NT) {
            int nb = buf + 2; if (nb >= 3) nb -= 3;
            prefetch(nb, (t+2)*64);
        }

        const uint32_t kb_a = sK + buf*KT*4 + fragoff;
        const uint32_t vb_a = sV + buf*KT*4 + fragoff;
        const uint32_t* km  = kms + buf*MB;
        buf++; if (buf == 3) buf = 0;

        // ---- S = (Q·log2e/8) @ K^T ----
        float s[8][4] = {};
        #pragma unroll
        for (int kk = 0; kk < 4; kk++) {
            #pragma unroll
            for (int jp = 0; jp < 4; jp++) {
                uint32_t b0, b1, b2, b3;
                ldsm4(b0, b1, b2, b3, kb_a + (jp*16*AP)*4 + kk*32);
                mma16(s[2*jp  ], aQ[kk][0], aQ[kk][1], aQ[kk][2], aQ[kk][3], b0, b1);
                mma16(s[2*jp+1], aQ[kk][0], aQ[kk][1], aQ[kk][2], aQ[kk][3], b2, b3);
            }
        }

        // ---- q-masked rows -> 0 (uniform softmax, l=2048) ----
        if (!q0ok) {
            #pragma unroll
            for (int j = 0; j < 8; j++) { s[j][0] = 0.0f; s[j][1] = 0.0f; }
        }
        if (!q1ok) {
            #pragma unroll
            for (int j = 0; j < 8; j++) { s[j][2] = 0.0f; s[j][3] = 0.0f; }
        }

        // ---- online softmax max (over raw s; masked keys only shift scale) ----
        float mx0 = -1e30f, mx1 = -1e30f;
        #pragma unroll
        for (int j = 0; j < 8; j++) {
            mx0 = fmaxf(mx0, fmaxf(s[j][0], s[j][1]));
            mx1 = fmaxf(mx1, fmaxf(s[j][2], s[j][3]));
        }
        mx0 = fmaxf(mx0, __shfl_xor_sync(0xffffffffu, mx0, 1));
        mx0 = fmaxf(mx0, __shfl_xor_sync(0xffffffffu, mx0, 2));
        mx1 = fmaxf(mx1, __shfl_xor_sync(0xffffffffu, mx1, 1));
        mx1 = fmaxf(mx1, __shfl_xor_sync(0xffffffffu, mx1, 2));

        if (__any_sync(0xffffffffu, (mx0 > m0) | (mx1 > m1))) {
            float nm0 = fmaxf(m0, mx0), nm1 = fmaxf(m1, mx1);
            float sc0 = ex2(m0 - nm0), sc1 = ex2(m1 - nm1);
            #pragma unroll
            for (int j = 0; j < 8; j++) {
                o[j][0] *= sc0; o[j][1] *= sc0;
                o[j][2] *= sc1; o[j][3] *= sc1;
            }
            ol[0] *= sc0; ol[1] *= sc0;
            ol[2] *= sc1; ol[3] *= sc1;
            m0 = nm0;  m1 = nm1;
        }

        // ---- exp2 (f16x2) -> masked A-frags -> PV mma + l-mma ----
        #pragma unroll
        for (int jj = 0; jj < 4; jj++) {
            uint32_t a0 = h2ex2(pkcvt(s[2*jj  ][0] - m0, s[2*jj  ][1] - m0));
            uint32_t a1 = h2ex2(pkcvt(s[2*jj  ][2] - m1, s[2*jj  ][3] - m1));
            uint32_t a2 = h2ex2(pkcvt(s[2*jj+1][0] - m0, s[2*jj+1][1] - m0));
            uint32_t a3 = h2ex2(pkcvt(s[2*jj+1][2] - m1, s[2*jj+1][3] - m1));

            uint32_t km_e = km[(2*jj  )*4 + qc];   // keys 16jj   + 2qc,+1
            uint32_t km_o = km[(2*jj+1)*4 + qc];   // keys 16jj+8 + 2qc,+1
            if (q0ok) { a0 = h2mul(a0, km_e); a2 = h2mul(a2, km_o); }
            if (q1ok) { a1 = h2mul(a1, km_e); a3 = h2mul(a3, km_o); }

            #pragma unroll
            for (int njp = 0; njp < 4; njp++) {
                uint32_t b0, b1, b2, b3;
                ldsm4(b0, b1, b2, b3, vb_a + (njp*16*AP)*4 + jj*32);
                mma16(o[2*njp  ], a0, a1, a2, a3, b0, b1);
                mma16(o[2*njp+1], a0, a1, a2, a3, b2, b3);
            }
            mma16(ol, a0, a1, a2, a3, bOnes, bOnes);   // l += row-sums
        }
    }

    // ---- epilogue: recover l from qc==0 lanes, normalize, write fp16 ----
    float lq0 = __shfl_sync(0xffffffffu, ol[0], lane & ~3);
    float lq1 = __shfl_sync(0xffffffffu, ol[2], lane & ~3);
    float inv0 = 1.0f / lq0, inv1 = 1.0f / lq1;
    int r0 = q0 + wrow + qr, r1 = r0 + 8;
    #pragma unroll
    for (int j = 0; j < 8; j++) {
        int d = h*64 + j*8 + qc*2;
        *(__half2*)(g_attnh + ((size_t)(bi*LL + r0))*DMODEL + d) =
            __floats2half2_rn(o[j][0]*inv0, o[j][1]*inv0);
        *(__half2*)(g_attnh + ((size_t)(bi*LL + r1))*DMODEL + d) =
            __floats2half2_rn(o[j][2]*inv1, o[j][3]*inv1);
    }
}

// ---------------------------------------------------------------------------
extern "C" void kernel_launch(void* const* d_in, const int* in_sizes, int n_in,
                              void* d_out, int out_size)
{
    const float* q  = (const float*)d_in[0];
    const float* k  = (const float*)d_in[1];
    const float* v  = (const float*)d_in[2];
    const float* tm = (const float*)d_in[3];
    const float* am = (const float*)d_in[4];
    const float* wq = (const float*)d_in[6];
    const float* bq = (const float*)d_in[7];
    const float* wk = (const float*)d_in[8];
    const float* bk = (const float*)d_in[9];
    const float* wv = (const float*)d_in[10];
    const float* bv = (const float*)d_in[11];
    const float* wo = (const float*)d_in[12];
    const float* bo = (const float*)d_in[13];
    float* out = (float*)d_out;

    __half *xq, *xk, *xv, *wh, *gq, *gk, *gv, *gattn;
    float *gcoef;
    cudaGetSymbolAddress((void**)&xq,    g_xq);
    cudaGetSymbolAddress((void**)&xk,    g_xk);
    cudaGetSymbolAddress((void**)&xv,    g_xv);
    cudaGetSymbolAddress((void**)&wh,    g_wh);
    cudaGetSymbolAddress((void**)&gq,    g_qh);
    cudaGetSymbolAddress((void**)&gk,    g_kh);
    cudaGetSymbolAddress((void**)&gv,    g_vh);
    cudaGetSymbolAddress((void**)&gattn, g_attnh);
    cudaGetSymbolAddress((void**)&gcoef, g_coef);

    cudaFuncSetAttribute(gemm_qkv, cudaFuncAttributeMaxDynamicSharedMemorySize, GEMM_SMEM);
    cudaFuncSetAttribute(gemm_out, cudaFuncAttributeMaxDynamicSharedMemorySize, GEMM_SMEM);
    cudaFuncSetAttribute(attn_kernel, cudaFuncAttributeMaxDynamicSharedMemorySize, ATTN_SMEM);

    const int NBIG = BB*LL*DMODEL/4;
    const int NW   = WSZ/4;
    CvtArgs ca;
    ca.src[0] = q;  ca.dst[0] = xq;         ca.n4[0] = NBIG;
    ca.src[1] = k;  ca.dst[1] = xk;         ca.n4[1] = NBIG;
    ca.src[2] = v;  ca.dst[2] = xv;         ca.n4[2] = NBIG;
    ca.src[3] = wq; ca.dst[3] = wh;         ca.n4[3] = NW;
    ca.src[4] = wk; ca.dst[4] = wh + WSZ;   ca.n4[4] = NW;
    ca.src[5] = wv; ca.dst[5] = wh + 2*WSZ; ca.n4[5] = NW;
    ca.src[6] = wo; ca.dst[6] = wh + 3*WSZ; ca.n4[6] = NW;
    cvt_kernel<<<dim3(256, 7), 256>>>(ca);

    coef_kernel<<<2, 1024>>>(tm, am);

    QkvArgs qkv;
    qkv.X[0] = xq; qkv.X[1] = xk; qkv.X[2] = xv;
    qkv.W[0] = wh; qkv.W[1] = wh + WSZ; qkv.W[2] = wh + 2*WSZ;
    qkv.bias[0] = bq; qkv.bias[1] = bk; qkv.bias[2] = bv;
    qkv.Y[0] = gq; qkv.Y[1] = gk; qkv.Y[2] = gv;
    qkv.mode[0] = 1; qkv.mode[1] = 2; qkv.mode[2] = 3;
    qkv.coef = gcoef;
    gemm_qkv<<<dim3(8, 32, 3), 256, GEMM_SMEM>>>(qkv);

    attn_kernel<<<dim3(16, 16), 256, ATTN_SMEM>>>();

    gemm_out<<<dim3(8, 32), 256, GEMM_SMEM>>>(gattn, wh + 3*WSZ, bo, out);
}